// round 1
// baseline (speedup 1.0000x reference)
#include <cuda_runtime.h>
#include <math.h>

#define B_   32
#define C_   64
#define H_   64
#define W_   64
#define K_   128
#define OH   62
#define OW   62
#define NPOS (B_*OH*OW)      // 123008
#define YSZ  ((size_t)B_*K_*OH*OW)  // 15745024
#define UPDSZ (K_*C_*9)      // 73728

__device__ float g_wnorm[576 * 128];   // layout [c*9+i*3+j][k]
__device__ int   g_winners[NPOS];

// ---------------------------------------------------------------------------
// Kernel 0a: weight normalization (per out-channel L2 norm over 576 elems),
// writes transposed layout [576][128] for coalesced conv staging.
// ---------------------------------------------------------------------------
__global__ void wnorm_kernel(const float* __restrict__ w) {
    int k = threadIdx.x;           // 128 threads, one per out channel
    float s = 0.f;
    #pragma unroll 8
    for (int i = 0; i < 576; i++) { float v = w[k*576 + i]; s += v*v; }
    float n = sqrtf(s);
    if (n == 0.f) n = 1.f;
    float inv = 1.f / n;
    for (int i = 0; i < 576; i++) g_wnorm[i*128 + k] = w[k*576 + i] * inv;
}

// ---------------------------------------------------------------------------
// Kernel 0b: zero the weight_update region of d_out (it is accumulated
// with atomics; d_out is poisoned before timing).
// ---------------------------------------------------------------------------
__global__ void zero_kernel(float* __restrict__ p, int n) {
    int i = blockIdx.x * blockDim.x + threadIdx.x;
    if (i < n) p[i] = 0.f;
}

// ---------------------------------------------------------------------------
// Kernel 1: fused conv (fp32, register-blocked) + bias + per-position argmax.
// Block tile: 1 batch image, 8 output rows x 16 output cols, ALL 128 channels.
// 256 threads: g = tid&15 -> channel group (8 ch), p = tid>>4 -> column.
// Each thread: acc[8 rows][8 channels] = 64 accumulators.
// Inner: per (c,kh,kw): 2x LDS.128 weights + 8 broadcast LDS x -> 64 FMA.
// ---------------------------------------------------------------------------
#define CCH 8
__global__ __launch_bounds__(256) void conv_kernel(
    const float* __restrict__ x, const float* __restrict__ bias,
    float* __restrict__ y)
{
    __shared__ float xs[CCH][10][18];
    __shared__ float ws[CCH*9][128];

    const int b   = blockIdx.z;
    const int oh0 = blockIdx.y * 8;
    const int ow0 = blockIdx.x * 16;
    const int tid = threadIdx.x;
    const int g   = tid & 15;
    const int p   = tid >> 4;

    float acc[8][8];
    #pragma unroll
    for (int i = 0; i < 8; i++)
        #pragma unroll
        for (int j = 0; j < 8; j++) acc[i][j] = 0.f;

    for (int c0 = 0; c0 < C_; c0 += CCH) {
        __syncthreads();
        // stage x slice: CCH channels, 10x18 window (zero-pad OOB; those
        // positions are never stored)
        for (int idx = tid; idx < CCH*10*18; idx += 256) {
            int cl  = idx / 180;
            int rem = idx - cl*180;
            int r   = rem / 18;
            int col = rem - r*18;
            int gr = oh0 + r, gc = ow0 + col;
            float v = 0.f;
            if (gr < H_ && gc < W_)
                v = x[(((size_t)b*C_ + c0 + cl)*H_ + gr)*W_ + gc];
            xs[cl][r][col] = v;
        }
        // stage weight slice: CCH*9 rows x 128 k, contiguous in g_wnorm
        {
            const float4* src = (const float4*)(g_wnorm + c0*9*128);
            float4* dst = (float4*)(&ws[0][0]);
            for (int idx = tid; idx < CCH*9*128/4; idx += 256)
                dst[idx] = src[idx];
        }
        __syncthreads();

        #pragma unroll 1
        for (int cl = 0; cl < CCH; cl++) {
            #pragma unroll
            for (int kh = 0; kh < 3; kh++) {
                #pragma unroll
                for (int kw = 0; kw < 3; kw++) {
                    float4 wa = *(const float4*)&ws[cl*9 + kh*3 + kw][g*8];
                    float4 wb = *(const float4*)&ws[cl*9 + kh*3 + kw][g*8 + 4];
                    #pragma unroll
                    for (int i = 0; i < 8; i++) {
                        float xv = xs[cl][i + kh][p + kw];
                        acc[i][0] += xv * wa.x;
                        acc[i][1] += xv * wa.y;
                        acc[i][2] += xv * wa.z;
                        acc[i][3] += xv * wa.w;
                        acc[i][4] += xv * wb.x;
                        acc[i][5] += xv * wb.y;
                        acc[i][6] += xv * wb.z;
                        acc[i][7] += xv * wb.w;
                    }
                }
            }
        }
    }

    // ---- epilogue: +bias, store y, argmax over 128 channels ----
    const int ow = ow0 + p;
    const bool colok = (ow < OW);
    float bv[8];
    #pragma unroll
    for (int j = 0; j < 8; j++) bv[j] = bias[g*8 + j];

    #pragma unroll 1
    for (int i = 0; i < 8; i++) {
        int oh = oh0 + i;
        bool ok = colok && (oh < OH);

        // local argmax over this thread's 8 channels (first-max on ties:
        // strict > with ascending j)
        float vmax;
        int   kmax;
        {
            float v0 = acc[i][0] + bv[0];
            acc[i][0] = v0; vmax = v0; kmax = g*8;
            #pragma unroll
            for (int j = 1; j < 8; j++) {
                float v = acc[i][j] + bv[j];
                acc[i][j] = v;
                if (v > vmax) { vmax = v; kmax = g*8 + j; }
            }
        }

        if (ok) {
            float* yp = y + (((size_t)b*K_ + g*8)*OH + oh)*OW + ow;
            #pragma unroll
            for (int j = 0; j < 8; j++) yp[(size_t)j*OH*OW] = acc[i][j];
        }

        // reduce across the 16 channel-groups; lanes [0..15]/[16..31] of a
        // warp each form one position (same p, same ok). Tie-break: lower k.
        #pragma unroll
        for (int off = 8; off >= 1; off >>= 1) {
            float ov = __shfl_down_sync(0xFFFFFFFFu, vmax, off, 16);
            int   oi = __shfl_down_sync(0xFFFFFFFFu, kmax, off, 16);
            if (ov > vmax || (ov == vmax && oi < kmax)) { vmax = ov; kmax = oi; }
        }
        if (ok && g == 0)
            g_winners[((size_t)b*OH + oh)*OW + ow] = kmax;
    }
}

// ---------------------------------------------------------------------------
// Kernel 2: Hebbian accumulation. Block (k, chunk): scan winners in chunk,
// accumulate matched 3x3x64 patches into shared acc[576], then one scaled
// atomicAdd sweep into d_out's update region.
// ---------------------------------------------------------------------------
__global__ __launch_bounds__(256) void hebb_kernel(
    const float* __restrict__ x, float* __restrict__ upd)
{
    const int k     = blockIdx.x;
    const int chunk = blockIdx.y;
    __shared__ float acc[576];
    for (int i = threadIdx.x; i < 576; i += 256) acc[i] = 0.f;
    __syncthreads();

    const int cs = NPOS / 8;              // 15376, divides evenly
    const int start = chunk * cs;
    const int end   = start + cs;
    for (int pp = start + threadIdx.x; pp < end; pp += 256) {
        if (g_winners[pp] == k) {
            int b  = pp / (OH*OW);
            int r  = pp - b*(OH*OW);
            int oh = r / OW;
            int ow = r - oh*OW;
            const float* xb = x + ((size_t)b*C_*H_ + oh)*W_ + ow;
            #pragma unroll 1
            for (int c = 0; c < C_; c++) {
                const float* xc = xb + (size_t)c*H_*W_;
                #pragma unroll
                for (int ii = 0; ii < 3; ii++)
                    #pragma unroll
                    for (int jj = 0; jj < 3; jj++)
                        atomicAdd(&acc[c*9 + ii*3 + jj], xc[ii*W_ + jj]);
            }
        }
    }
    __syncthreads();

    const float s = 1.0f / (123008.0f + 1e-8f);
    for (int i = threadIdx.x; i < 576; i += 256)
        atomicAdd(&upd[k*576 + i], acc[i] * s);
}

// ---------------------------------------------------------------------------
// Launch: d_in[0]=x [32,64,64,64], d_in[1]=weight [128,64,3,3],
// d_in[2]=bias [128]. d_out = y (15745024 floats) ++ weight_update (73728).
// ---------------------------------------------------------------------------
extern "C" void kernel_launch(void* const* d_in, const int* in_sizes, int n_in,
                              void* d_out, int out_size) {
    const float* x    = (const float*)d_in[0];
    const float* w    = (const float*)d_in[1];
    const float* bias = (const float*)d_in[2];
    float* y   = (float*)d_out;
    float* upd = y + YSZ;

    wnorm_kernel<<<1, 128>>>(w);
    zero_kernel<<<(UPDSZ + 255)/256, 256>>>(upd, UPDSZ);
    conv_kernel<<<dim3(4, 8, B_), 256>>>(x, bias, y);
    hebb_kernel<<<dim3(K_, 8), 256>>>(x, upd);
}

// round 2
// speedup vs baseline: 2.9851x; 2.9851x over previous
#include <cuda_runtime.h>
#include <math.h>

#define B_   32
#define C_   64
#define H_   64
#define W_   64
#define K_   128
#define OH   62
#define OW   62
#define NPOS (B_*OH*OW)             // 123008
#define YSZ  ((size_t)B_*K_*OH*OW)  // 15745024
#define UPDSZ (K_*C_*9)             // 73728

__device__ float g_wnorm[576 * 128];   // layout [c*9+i*3+j][k]
__device__ int   g_winners[NPOS];

typedef unsigned long long ull;

__device__ __forceinline__ ull pack2(float v) {
    ull r;
    asm("mov.b64 %0, {%1, %1};" : "=l"(r) : "f"(v));
    return r;
}
__device__ __forceinline__ void fma2(ull& d, ull a, ull b) {
    asm("fma.rn.f32x2 %0, %1, %2, %0;" : "+l"(d) : "l"(a), "l"(b));
}
__device__ __forceinline__ void unpack2(ull v, float& lo, float& hi) {
    asm("mov.b64 {%0, %1}, %2;" : "=f"(lo), "=f"(hi) : "l"(v));
}

// ---------------------------------------------------------------------------
// Kernel 0a: weight normalization, transposed to [576][128].
// ---------------------------------------------------------------------------
__global__ void wnorm_kernel(const float* __restrict__ w) {
    int k = threadIdx.x;
    float s = 0.f;
    #pragma unroll 8
    for (int i = 0; i < 576; i++) { float v = w[k*576 + i]; s += v*v; }
    float n = sqrtf(s);
    if (n == 0.f) n = 1.f;
    float inv = 1.f / n;
    for (int i = 0; i < 576; i++) g_wnorm[i*128 + k] = w[k*576 + i] * inv;
}

__global__ void zero_kernel(float* __restrict__ p, int n) {
    int i = blockIdx.x * blockDim.x + threadIdx.x;
    if (i < n) p[i] = 0.f;
}

// ---------------------------------------------------------------------------
// Kernel 1: conv + bias + argmax.
// p = tid&15 (column), g = tid>>4 (channel group of 8) -> weight LDS.128 is
// broadcast within 16 lanes (2 distinct lines/warp, conflict-free).
// Accumulators are packed f32x2 (channel pairs): 32 FFMA2 per (c,kh,kw).
// ---------------------------------------------------------------------------
#define CCH 8
__global__ __launch_bounds__(256) void conv_kernel(
    const float* __restrict__ x, const float* __restrict__ bias,
    float* __restrict__ y)
{
    __shared__ float xs[CCH][10][18];
    __shared__ float ws[CCH*9][128];
    __shared__ float rv[256];
    __shared__ int   rk[256];

    const int b   = blockIdx.z;
    const int oh0 = blockIdx.y * 8;
    const int ow0 = blockIdx.x * 16;
    const int tid = threadIdx.x;
    const int p   = tid & 15;     // output column within tile
    const int g   = tid >> 4;     // channel group (8 channels)

    ull acc[8][4];
    #pragma unroll
    for (int i = 0; i < 8; i++)
        #pragma unroll
        for (int j = 0; j < 4; j++) acc[i][j] = 0ULL;

    for (int c0 = 0; c0 < C_; c0 += CCH) {
        __syncthreads();
        // stage x slice: CCH channels, 10x18 window (zero-pad OOB)
        for (int idx = tid; idx < CCH*10*18; idx += 256) {
            int cl  = idx / 180;
            int rem = idx - cl*180;
            int r   = rem / 18;
            int col = rem - r*18;
            int gr = oh0 + r, gc = ow0 + col;
            float v = 0.f;
            if (gr < H_ && gc < W_)
                v = x[(((size_t)b*C_ + c0 + cl)*H_ + gr)*W_ + gc];
            xs[cl][r][col] = v;
        }
        // stage weight slice (contiguous in g_wnorm)
        {
            const float4* src = (const float4*)(g_wnorm + c0*9*128);
            float4* dst = (float4*)(&ws[0][0]);
            for (int idx = tid; idx < CCH*9*128/4; idx += 256)
                dst[idx] = src[idx];
        }
        __syncthreads();

        #pragma unroll 1
        for (int cl = 0; cl < CCH; cl++) {
            #pragma unroll
            for (int kh = 0; kh < 3; kh++) {
                #pragma unroll
                for (int kw = 0; kw < 3; kw++) {
                    const ulonglong2* wp =
                        (const ulonglong2*)&ws[cl*9 + kh*3 + kw][g*8];
                    ulonglong2 w0 = wp[0];   // channels g*8+0..3 as 2 pairs
                    ulonglong2 w1 = wp[1];   // channels g*8+4..7
                    #pragma unroll
                    for (int i = 0; i < 8; i++) {
                        ull xx = pack2(xs[cl][i + kh][p + kw]);
                        fma2(acc[i][0], xx, w0.x);
                        fma2(acc[i][1], xx, w0.y);
                        fma2(acc[i][2], xx, w1.x);
                        fma2(acc[i][3], xx, w1.y);
                    }
                }
            }
        }
    }

    // ---- epilogue: +bias, store y, argmax over 128 channels ----
    const int ow = ow0 + p;
    const bool colok = (ow < OW);
    float bv[8];
    #pragma unroll
    for (int j = 0; j < 8; j++) bv[j] = bias[g*8 + j];

    #pragma unroll 1
    for (int i = 0; i < 8; i++) {
        int oh = oh0 + i;
        bool ok = colok && (oh < OH);

        float v[8];
        #pragma unroll
        for (int j = 0; j < 4; j++) {
            float lo, hi;
            unpack2(acc[i][j], lo, hi);
            v[2*j]   = lo + bv[2*j];
            v[2*j+1] = hi + bv[2*j+1];
        }

        // local argmax (first-max on ties: strict >, ascending j)
        float vmax = v[0];
        int   kmax = g*8;
        #pragma unroll
        for (int j = 1; j < 8; j++)
            if (v[j] > vmax) { vmax = v[j]; kmax = g*8 + j; }

        if (ok) {
            float* yp = y + (((size_t)b*K_ + g*8)*OH + oh)*OW + ow;
            #pragma unroll
            for (int j = 0; j < 8; j++) yp[(size_t)j*OH*OW] = v[j];
        }

        // cross-group reduction via shared (16 groups share column p)
        __syncthreads();
        rv[tid] = vmax; rk[tid] = kmax;
        __syncthreads();
        if (g == 0 && ok) {
            float bm = rv[p]; int km = rk[p];
            #pragma unroll 1
            for (int j = 1; j < 16; j++) {
                float o = rv[j*16 + p];
                if (o > bm) { bm = o; km = rk[j*16 + p]; }
                else if (o == bm && rk[j*16 + p] < km) km = rk[j*16 + p];
            }
            g_winners[((size_t)b*OH + oh)*OW + ow] = km;
        }
    }
}

// ---------------------------------------------------------------------------
// Kernel 2: Hebbian accumulation, list-based. Block (k, chunk) scans its
// winner window 256 at a time, appends matches to a shared list, then all
// threads accumulate their OWN fixed patch elements (tid, tid+256, tid+512)
// in registers — no atomics in the hot loop.
// ---------------------------------------------------------------------------
__global__ __launch_bounds__(256) void hebb_kernel(
    const float* __restrict__ x, float* __restrict__ upd)
{
    const int k     = blockIdx.x;
    const int chunk = blockIdx.y;
    const int tid   = threadIdx.x;
    __shared__ int list[256];
    __shared__ int cnt;

    const int e0 = tid, e1 = tid + 256, e2 = tid + 512;
    const int off0 = (e0/9)*H_*W_ + ((e0%9)/3)*W_ + (e0%3);
    const int off1 = (e1/9)*H_*W_ + ((e1%9)/3)*W_ + (e1%3);
    const int off2 = (e2 < 576) ? (e2/9)*H_*W_ + ((e2%9)/3)*W_ + (e2%3) : 0;
    float a0 = 0.f, a1 = 0.f, a2 = 0.f;

    const int cs    = NPOS / 8;          // 15376
    const int start = chunk * cs;

    for (int w0 = 0; w0 < cs; w0 += 256) {
        if (tid == 0) cnt = 0;
        __syncthreads();
        int pp = start + w0 + tid;
        if (w0 + tid < cs && g_winners[pp] == k) {
            int slot = atomicAdd(&cnt, 1);
            list[slot] = pp;
        }
        __syncthreads();
        int m = cnt;
        #pragma unroll 1
        for (int t = 0; t < m; t++) {
            int pos = list[t];
            int b  = pos / (OH*OW);
            int r  = pos - b*(OH*OW);
            int oh = r / OW;
            int ow = r - oh*OW;
            const float* xb = x + (size_t)b*C_*H_*W_ + oh*W_ + ow;
            a0 += xb[off0];
            a1 += xb[off1];
            if (e2 < 576) a2 += xb[off2];
        }
    }

    const float s = 1.0f / (123008.0f + 1e-8f);
    atomicAdd(&upd[k*576 + e0], a0 * s);
    atomicAdd(&upd[k*576 + e1], a1 * s);
    if (e2 < 576) atomicAdd(&upd[k*576 + e2], a2 * s);
}

// ---------------------------------------------------------------------------
extern "C" void kernel_launch(void* const* d_in, const int* in_sizes, int n_in,
                              void* d_out, int out_size) {
    const float* x    = (const float*)d_in[0];
    const float* w    = (const float*)d_in[1];
    const float* bias = (const float*)d_in[2];
    float* y   = (float*)d_out;
    float* upd = y + YSZ;

    wnorm_kernel<<<1, 128>>>(w);
    zero_kernel<<<(UPDSZ + 255)/256, 256>>>(upd, UPDSZ);
    conv_kernel<<<dim3(4, 8, B_), 256>>>(x, bias, y);
    hebb_kernel<<<dim3(K_, 8), 256>>>(x, upd);
}

// round 9
// speedup vs baseline: 4.6470x; 1.5567x over previous
#include <cuda_runtime.h>
#include <cuda_bf16.h>
#include <cstdint>
#include <math.h>

#define B_    32
#define C_    64
#define H_    64
#define W_    64
#define K_    128
#define OH    62
#define OW    62
#define NPOS  (B_*OH*OW)             // 123008
#define YSZ   ((size_t)B_*K_*OH*OW)  // 15745024
#define UPDSZ (K_*C_*9)              // 73728
#define AMB_CAP 32768

// ---------------------------------------------------------------------------
// device globals
// ---------------------------------------------------------------------------
__device__ __nv_bfloat16 g_xh[(size_t)B_*C_*H_*W_];
__device__ __nv_bfloat16 g_xl[(size_t)B_*C_*H_*W_];
__device__ __nv_bfloat16 g_wpack[9 * 2*4*128*8*2];    // b-frag packed, 9 x 32KB
__device__ float g_wnf[K_*576];                       // normalized fp32 weights (R2-bit)
__device__ int g_winners[NPOS];
__device__ unsigned int g_ambcnt;
__device__ unsigned int g_amb[AMB_CAP];               // pos | k1<<17 | k2<<24
__device__ int g_kcnt[K_];
__device__ int g_klist[(size_t)K_*NPOS];

// ---------------------------------------------------------------------------
// helpers
// ---------------------------------------------------------------------------
__device__ __forceinline__ uint32_t smem_to_u32(const void* p) {
    uint32_t a;
    asm("{ .reg .u64 t; cvta.to.shared.u64 t, %1; cvt.u32.u64 %0, t; }" : "=r"(a) : "l"(p));
    return a;
}
__device__ __forceinline__ void ldmx4(uint32_t* r, uint32_t addr) {
    asm volatile("ldmatrix.sync.aligned.m8n8.x4.shared.b16 {%0,%1,%2,%3}, [%4];"
                 : "=r"(r[0]), "=r"(r[1]), "=r"(r[2]), "=r"(r[3]) : "r"(addr));
}
__device__ __forceinline__ void lds64(uint32_t* r, uint32_t addr) {
    asm volatile("ld.shared.v2.u32 {%0,%1}, [%2];" : "=r"(r[0]), "=r"(r[1]) : "r"(addr));
}
__device__ __forceinline__ void mma16816(float* c, const uint32_t* a, const uint32_t* b) {
    asm volatile("mma.sync.aligned.m16n8k16.row.col.f32.bf16.bf16.f32 "
                 "{%0,%1,%2,%3}, {%4,%5,%6,%7}, {%8,%9}, {%0,%1,%2,%3};"
                 : "+f"(c[0]), "+f"(c[1]), "+f"(c[2]), "+f"(c[3])
                 : "r"(a[0]), "r"(a[1]), "r"(a[2]), "r"(a[3]), "r"(b[0]), "r"(b[1]));
}

// ---------------------------------------------------------------------------
__global__ void prep_x_kernel(const float* __restrict__ x) {
    size_t i = (size_t)blockIdx.x * blockDim.x + threadIdx.x;
    if (i >= (size_t)B_*C_*H_*W_) return;
    float v = x[i];
    __nv_bfloat16 h = __float2bfloat16(v);
    __nv_bfloat16 l = __float2bfloat16(v - __bfloat162float(h));
    g_xh[i] = h;
    g_xl[i] = l;
}

// prep_w: R2-bit fp32 normalization (sequential fmaf norm, 1.0f/sqrtf div),
// + bf16 split + b-frag pack + fp32 copy for the refine replay.
__global__ void prep_w_kernel(const float* __restrict__ w) {
    int n  = threadIdx.x;
    int ij = blockIdx.x;
    float s = 0.f;
    for (int i = 0; i < 576; i++) { float v = w[n*576 + i]; s = fmaf(v, v, s); }
    float nm = sqrtf(s);
    if (nm == 0.f) nm = 1.f;
    float inv = 1.0f / nm;
    for (int c = 0; c < C_; c++) {
        float v = w[n*576 + c*9 + ij] * inv;
        g_wnf[n*576 + c*9 + ij] = v;
        __nv_bfloat16 h = __float2bfloat16(v);
        __nv_bfloat16 l = __float2bfloat16(v - __bfloat162float(h));
        int kc   = c >> 4;
        int cc   = c & 15;
        int widx = ((cc >> 1) & 3) * 2 + (cc >> 3);
        int half = cc & 1;
        size_t base = ((((size_t)ij*2 + 0)*4 + kc)*128 + n)*8 + widx;
        g_wpack[base*2 + half] = h;
        base = ((((size_t)ij*2 + 1)*4 + kc)*128 + n)*8 + widx;
        g_wpack[base*2 + half] = l;
    }
}

__global__ void zero_kernel(float* __restrict__ upd) {
    int i = blockIdx.x * blockDim.x + threadIdx.x;
    if (i < UPDSZ) upd[i] = 0.f;
    if (i < K_) g_kcnt[i] = 0;
    if (i == 0) g_ambcnt = 0;
}

// ---------------------------------------------------------------------------
// conv_mma: HMMA GEMM. CTA = (b, 2 output rows) -> 128 pos x 128 k.
// ---------------------------------------------------------------------------
#define SOFF_BIAS 0
#define SOFF_TH   1024
#define SOFF_TL   33792
#define SOFF_W    66560
#define SOFF_D    1024
#define SMEM_BYTES 99328

__global__ void __launch_bounds__(256) conv_mma_kernel(
    const float* __restrict__ bias, float* __restrict__ y)
{
    extern __shared__ unsigned char smem[];
    const uint32_t sb = smem_to_u32(smem);
    const int tid = threadIdx.x;
    const int l   = tid & 31;
    const int wid = tid >> 5;
    const int wm  = wid >> 2;
    const int wn  = wid & 3;
    const int b   = blockIdx.y;
    const int oh0 = blockIdx.x * 2;

    if (tid < 128) ((float*)(smem + SOFF_BIAS))[tid] = bias[tid];

    for (int idx = tid; idx < C_*4*16; idx += 256) {
        int c    = idx >> 6;
        int row  = (idx >> 4) & 3;
        int col4 = (idx & 15) * 4;
        size_t gi = (((size_t)b*C_ + c)*H_ + (oh0 + row))*W_ + col4;
        const __nv_bfloat16* ph = g_xh + gi;
        const __nv_bfloat16* pl = g_xl + gi;
        #pragma unroll
        for (int q = 0; q < 4; q++) {
            int col = col4 + q;
            int rowIdx = row*64 + col;
            uint32_t off = (uint32_t)(rowIdx*128 + c*2) ^ (uint32_t)((rowIdx & 7) << 4);
            *(__nv_bfloat16*)(smem + SOFF_TH + off) = ph[q];
            *(__nv_bfloat16*)(smem + SOFF_TL + off) = pl[q];
        }
    }

    float acc[4][4][4] = {};
    const int lrow_lo = (l & 7) + ((l >> 3) & 1) * 8;
    const uint32_t khalf = (uint32_t)((l >> 4) * 16);

    #pragma unroll 1
    for (int s = 0; s < 9; s++) {
        const int i = s / 3, j = s - 3*(s/3);
        __syncthreads();
        {
            const uint4* src = (const uint4*)((const __nv_bfloat16*)g_wpack + (size_t)s*16384);
            uint4* dst = (uint4*)(smem + SOFF_W);
            #pragma unroll
            for (int t = 0; t < 8; t++) dst[tid + t*256] = src[tid + t*256];
        }
        __syncthreads();

        uint32_t abase[4], asw[4];
        #pragma unroll
        for (int mt = 0; mt < 4; mt++) {
            int m  = wm*64 + mt*16 + lrow_lo;
            int nr = m >> 6, nc = m & 63;
            int pc = nc + j; if (pc > 63) pc = 63;
            int rowIdx = (nr + i)*64 + pc;
            abase[mt] = sb + SOFF_TH + (uint32_t)(rowIdx*128);
            asw[mt]   = (uint32_t)((rowIdx & 7) << 4);
        }

        const uint32_t swb = sb + SOFF_W;
        #pragma unroll 1
        for (int kc = 0; kc < 4; kc++) {
            const uint32_t koff = (uint32_t)kc * 32;
            uint32_t ah[4][4], bh[4][2];
            #pragma unroll
            for (int mt = 0; mt < 4; mt++)
                ldmx4(ah[mt], abase[mt] + ((khalf + koff) ^ asw[mt]));
            #pragma unroll
            for (int nt = 0; nt < 4; nt++) {
                int n = wn*32 + nt*8 + (l >> 2);
                lds64(bh[nt], swb + (uint32_t)((((0*4 + kc)*128 + n)*8 + (l & 3)*2) * 4));
            }
            #pragma unroll
            for (int mt = 0; mt < 4; mt++)
                #pragma unroll
                for (int nt = 0; nt < 4; nt++)
                    mma16816(acc[mt][nt], ah[mt], bh[nt]);
            {
                uint32_t al[4][4];
                #pragma unroll
                for (int mt = 0; mt < 4; mt++)
                    ldmx4(al[mt], abase[mt] + 32768 + ((khalf + koff) ^ asw[mt]));
                #pragma unroll
                for (int mt = 0; mt < 4; mt++)
                    #pragma unroll
                    for (int nt = 0; nt < 4; nt++)
                        mma16816(acc[mt][nt], al[mt], bh[nt]);
            }
            {
                uint32_t bl[4][2];
                #pragma unroll
                for (int nt = 0; nt < 4; nt++) {
                    int n = wn*32 + nt*8 + (l >> 2);
                    lds64(bl[nt], swb + (uint32_t)((((1*4 + kc)*128 + n)*8 + (l & 3)*2) * 4));
                }
                #pragma unroll
                for (int mt = 0; mt < 4; mt++)
                    #pragma unroll
                    for (int nt = 0; nt < 4; nt++)
                        mma16816(acc[mt][nt], ah[mt], bl[nt]);
            }
        }
    }

    // ---- epilogue: frags -> smem D[128][130] ----
    __syncthreads();
    float* D = (float*)(smem + SOFF_D);
    {
        const int r  = l >> 2;
        const int cq = (l & 3) * 2;
        #pragma unroll
        for (int mt = 0; mt < 4; mt++)
            #pragma unroll
            for (int nt = 0; nt < 4; nt++) {
                int pos = wm*64 + mt*16 + r;
                int k   = wn*32 + nt*8 + cq;
                *(float2*)&D[pos*130 + k]       = make_float2(acc[mt][nt][0], acc[mt][nt][1]);
                *(float2*)&D[(pos + 8)*130 + k] = make_float2(acc[mt][nt][2], acc[mt][nt][3]);
            }
    }
    __syncthreads();

    // ---- per-thread: bias + top-2 argmax + y store; flag near-ties ----
    {
        const int p2   = tid >> 1;
        const int kh2  = (tid & 1) * 64;
        const int nrow = p2 >> 6, ncol = p2 & 63;
        const int oh = oh0 + nrow, ow = ncol;
        const bool valid = (ncol < OW);
        const float* bs = (const float*)(smem + SOFF_BIAS);
        float v1 = -INFINITY, v2 = -INFINITY;
        int   k1 = 0, k2 = 0;
        float* yb = y + ((size_t)b*K_)*OH*OW + (size_t)oh*OW + ow;
        #pragma unroll 4
        for (int k = kh2; k < kh2 + 64; k += 2) {
            float2 d = *(float2*)&D[p2*130 + k];
            float a0 = d.x + bs[k];
            float a1 = d.y + bs[k+1];
            if (a0 > v1) { v2 = v1; k2 = k1; v1 = a0; k1 = k; }
            else if (a0 > v2) { v2 = a0; k2 = k; }
            if (a1 > v1) { v2 = v1; k2 = k1; v1 = a1; k1 = k + 1; }
            else if (a1 > v2) { v2 = a1; k2 = k + 1; }
            if (valid) {
                yb[(size_t)k*OH*OW]     = a0;
                yb[(size_t)(k+1)*OH*OW] = a1;
            }
        }
        __syncthreads();
        float* rv = (float*)(smem + SOFF_D);
        int*   rk = (int*)(smem + SOFF_D + 4096);
        rv[tid*2] = v1; rv[tid*2+1] = v2;
        rk[tid*2] = k1; rk[tid*2+1] = k2;
        __syncthreads();
        if ((tid & 1) == 0 && valid) {
            float w1 = rv[(tid+1)*2], w2 = rv[(tid+1)*2+1];
            int   j1 = rk[(tid+1)*2], j2 = rk[(tid+1)*2+1];
            float t1, t2; int m1, m2;
            if (w1 > v1) { t1 = w1; m1 = j1; t2 = (v1 > w2) ? v1 : w2; m2 = (v1 > w2) ? k1 : j2; }
            else         { t1 = v1; m1 = k1; t2 = (w1 > v2) ? w1 : v2; m2 = (w1 > v2) ? j1 : k2; }
            int pos = (b*OH + oh)*OW + ow;
            g_winners[pos] = m1;
            if (t1 - t2 < 4e-3f) {
                unsigned int slot = atomicAdd(&g_ambcnt, 1u);
                if (slot < AMB_CAP)
                    g_amb[slot] = (unsigned int)pos | ((unsigned int)m1 << 17)
                                                   | ((unsigned int)m2 << 24);
            }
        }
    }
}

// ---------------------------------------------------------------------------
// refine: R2 REPLAY. For each flagged position, recompute both candidate
// dot products exactly the way the (verified-passing) R2 fp32 kernel did:
// sequential fp32 fmaf chain over (c asc, kh, kw), R2-bit normalized weights,
// first-max tie-break (lower k wins ties). This reproduces the winner field
// that passed at 5.7e-7, independent of the reference's internal rounding.
// One thread per flagged entry.
// ---------------------------------------------------------------------------
__global__ void __launch_bounds__(128) refine_kernel(const float* __restrict__ x) {
    unsigned int total = g_ambcnt;
    if (total > AMB_CAP) total = AMB_CAP;
    unsigned int stride = gridDim.x * blockDim.x;
    for (unsigned int e = blockIdx.x * blockDim.x + threadIdx.x; e < total; e += stride) {
        unsigned int ent = g_amb[e];
        int pos = (int)(ent & 0x1FFFF);
        int ka  = (int)((ent >> 17) & 0x7F);
        int kb  = (int)((ent >> 24) & 0x7F);
        int bb = pos / (OH*OW);
        int r  = pos - bb*(OH*OW);
        int oh = r / OW;
        int ow = r - oh*OW;
        const float* xb = x + (size_t)bb*C_*H_*W_ + (size_t)oh*W_ + ow;
        const float* wa = g_wnf + ka*576;
        const float* wb = g_wnf + kb*576;
        float sa = 0.f, sb2 = 0.f;
        #pragma unroll 1
        for (int c = 0; c < C_; c++) {
            const float* xc = xb + (size_t)c*H_*W_;
            const float* wac = wa + c*9;
            const float* wbc = wb + c*9;
            #pragma unroll
            for (int ii = 0; ii < 3; ii++)
                #pragma unroll
                for (int jj = 0; jj < 3; jj++) {
                    float xv = xc[ii*W_ + jj];
                    sa  = fmaf(xv, wac[ii*3 + jj], sa);
                    sb2 = fmaf(xv, wbc[ii*3 + jj], sb2);
                }
        }
        int klo, khi; float dlo, dhi;
        if (ka < kb) { klo = ka; khi = kb; dlo = sa; dhi = sb2; }
        else         { klo = kb; khi = ka; dlo = sb2; dhi = sa; }
        g_winners[pos] = (dhi > dlo) ? khi : klo;   // first-max: ties -> lower k
    }
}

// ---------------------------------------------------------------------------
__global__ void __launch_bounds__(256) bucket_kernel() {
    int pos = blockIdx.x * blockDim.x + threadIdx.x;
    if (pos >= NPOS) return;
    int k = g_winners[pos];
    int slot = atomicAdd(&g_kcnt[k], 1);
    g_klist[(size_t)k*NPOS + slot] = pos;
}

// ---------------------------------------------------------------------------
__global__ void __launch_bounds__(256) hebb_kernel(
    const float* __restrict__ x, float* __restrict__ upd)
{
    const int k   = blockIdx.x;
    const int ch  = blockIdx.y;
    const int tid = threadIdx.x;
    const int n   = g_kcnt[k];
    const int lo  = (int)((long long)n * ch / 16);
    const int hi  = (int)((long long)n * (ch + 1) / 16);

    const int e0 = tid, e1 = tid + 256, e2 = tid + 512;
    const int off0 = (e0/9)*H_*W_ + ((e0%9)/3)*W_ + (e0%3);
    const int off1 = (e1/9)*H_*W_ + ((e1%9)/3)*W_ + (e1%3);
    const int off2 = (e2 < 576) ? (e2/9)*H_*W_ + ((e2%9)/3)*W_ + (e2%3) : 0;
    float a0 = 0.f, a1 = 0.f, a2 = 0.f;

    const int* list = g_klist + (size_t)k*NPOS;
    #pragma unroll 1
    for (int t = lo; t < hi; t++) {
        int pos = list[t];
        int bb = pos / (OH*OW);
        int r  = pos - bb*(OH*OW);
        int oh = r / OW;
        int ow = r - oh*OW;
        const float* xb = x + (size_t)bb*C_*H_*W_ + oh*W_ + ow;
        a0 += xb[off0];
        a1 += xb[off1];
        if (e2 < 576) a2 += xb[off2];
    }
    const float s = 1.0f / (123008.0f + 1e-8f);
    if (lo < hi) {
        atomicAdd(&upd[k*576 + e0], a0 * s);
        atomicAdd(&upd[k*576 + e1], a1 * s);
        if (e2 < 576) atomicAdd(&upd[k*576 + e2], a2 * s);
    }
}

// ---------------------------------------------------------------------------
extern "C" void kernel_launch(void* const* d_in, const int* in_sizes, int n_in,
                              void* d_out, int out_size) {
    const float* x    = (const float*)d_in[0];
    const float* w    = (const float*)d_in[1];
    const float* bias = (const float*)d_in[2];
    float* y   = (float*)d_out;
    float* upd = y + YSZ;

    cudaFuncSetAttribute(conv_mma_kernel,
                         cudaFuncAttributeMaxDynamicSharedMemorySize, SMEM_BYTES);

    prep_x_kernel<<<(int)(((size_t)B_*C_*H_*W_ + 255)/256), 256>>>(x);
    prep_w_kernel<<<9, 128>>>(w);
    zero_kernel<<<(UPDSZ + 255)/256, 256>>>(upd);
    conv_mma_kernel<<<dim3(OH/2, B_), 256, SMEM_BYTES>>>(bias, y);
    refine_kernel<<<128, 128>>>(x);
    bucket_kernel<<<(NPOS + 255)/256, 256>>>();
    hebb_kernel<<<dim3(K_, 16), 256>>>(x, upd);
}

// round 10
// speedup vs baseline: 4.9564x; 1.0666x over previous
#include <cuda_runtime.h>
#include <cuda_bf16.h>
#include <cstdint>
#include <math.h>

#define B_    32
#define C_    64
#define H_    64
#define W_    64
#define K_    128
#define OH    62
#define OW    62
#define NPOS  (B_*OH*OW)             // 123008
#define YSZ   ((size_t)B_*K_*OH*OW)  // 15745024
#define UPDSZ (K_*C_*9)              // 73728
#define AMB_CAP 32768

// ---------------------------------------------------------------------------
// device globals
// ---------------------------------------------------------------------------
__device__ __nv_bfloat16 g_xh[(size_t)B_*C_*H_*W_];
__device__ __nv_bfloat16 g_xl[(size_t)B_*C_*H_*W_];
__device__ float g_xt[(size_t)B_*H_*W_*C_];           // NHWC fp32 copy for hebb
__device__ __nv_bfloat16 g_wpack[9 * 2*4*128*8*2];    // b-frag packed, 9 x 32KB
__device__ float g_wnf[K_*576];                       // normalized fp32 weights (R2-bit)
__device__ int g_winners[NPOS];
__device__ unsigned int g_ambcnt;
__device__ unsigned int g_amb[AMB_CAP];               // pos | k1<<17 | k2<<24
__device__ int g_kcnt[K_];
__device__ int g_klist[(size_t)K_*NPOS];

// ---------------------------------------------------------------------------
// helpers
// ---------------------------------------------------------------------------
__device__ __forceinline__ uint32_t smem_to_u32(const void* p) {
    uint32_t a;
    asm("{ .reg .u64 t; cvta.to.shared.u64 t, %1; cvt.u32.u64 %0, t; }" : "=r"(a) : "l"(p));
    return a;
}
__device__ __forceinline__ void ldmx4(uint32_t* r, uint32_t addr) {
    asm volatile("ldmatrix.sync.aligned.m8n8.x4.shared.b16 {%0,%1,%2,%3}, [%4];"
                 : "=r"(r[0]), "=r"(r[1]), "=r"(r[2]), "=r"(r[3]) : "r"(addr));
}
__device__ __forceinline__ void lds64(uint32_t* r, uint32_t addr) {
    asm volatile("ld.shared.v2.u32 {%0,%1}, [%2];" : "=r"(r[0]), "=r"(r[1]) : "r"(addr));
}
__device__ __forceinline__ void mma16816(float* c, const uint32_t* a, const uint32_t* b) {
    asm volatile("mma.sync.aligned.m16n8k16.row.col.f32.bf16.bf16.f32 "
                 "{%0,%1,%2,%3}, {%4,%5,%6,%7}, {%8,%9}, {%0,%1,%2,%3};"
                 : "+f"(c[0]), "+f"(c[1]), "+f"(c[2]), "+f"(c[3])
                 : "r"(a[0]), "r"(a[1]), "r"(a[2]), "r"(a[3]), "r"(b[0]), "r"(b[1]));
}

// ---------------------------------------------------------------------------
__global__ void prep_x_kernel(const float* __restrict__ x) {
    size_t i = (size_t)blockIdx.x * blockDim.x + threadIdx.x;
    if (i >= (size_t)B_*C_*H_*W_) return;
    float v = x[i];
    __nv_bfloat16 h = __float2bfloat16(v);
    __nv_bfloat16 l = __float2bfloat16(v - __bfloat162float(h));
    g_xh[i] = h;
    g_xl[i] = l;
}

// ---------------------------------------------------------------------------
// transpose: x NCHW -> g_xt NHWC, smem-tiled 64x64 per (b,h), both sides
// coalesced, bank-conflict-free (65-pad).
// ---------------------------------------------------------------------------
__global__ void __launch_bounds__(256) transpose_kernel(const float* __restrict__ x) {
    __shared__ float t[64][65];
    const int bh = blockIdx.x;          // b*H + h
    const int b  = bh >> 6;
    const int h  = bh & 63;
    const int tid = threadIdx.x;
    // read: [c][w], w coalesced
    for (int idx = tid; idx < 4096; idx += 256) {
        int c = idx >> 6, w = idx & 63;
        t[c][w] = x[(((size_t)(b*64 + c))*64 + h)*64 + w];
    }
    __syncthreads();
    // write: [w][c], c coalesced
    for (int idx = tid; idx < 4096; idx += 256) {
        int w = idx >> 6, c = idx & 63;
        g_xt[(((size_t)(b*64 + h))*64 + w)*64 + c] = t[c][w];
    }
}

// prep_w: R2-bit fp32 normalization (sequential fmaf norm, 1.0f/sqrtf div),
// + bf16 split + b-frag pack + fp32 copy for the refine replay.
__global__ void prep_w_kernel(const float* __restrict__ w) {
    int n  = threadIdx.x;
    int ij = blockIdx.x;
    float s = 0.f;
    for (int i = 0; i < 576; i++) { float v = w[n*576 + i]; s = fmaf(v, v, s); }
    float nm = sqrtf(s);
    if (nm == 0.f) nm = 1.f;
    float inv = 1.0f / nm;
    for (int c = 0; c < C_; c++) {
        float v = w[n*576 + c*9 + ij] * inv;
        g_wnf[n*576 + c*9 + ij] = v;
        __nv_bfloat16 h = __float2bfloat16(v);
        __nv_bfloat16 l = __float2bfloat16(v - __bfloat162float(h));
        int kc   = c >> 4;
        int cc   = c & 15;
        int widx = ((cc >> 1) & 3) * 2 + (cc >> 3);
        int half = cc & 1;
        size_t base = ((((size_t)ij*2 + 0)*4 + kc)*128 + n)*8 + widx;
        g_wpack[base*2 + half] = h;
        base = ((((size_t)ij*2 + 1)*4 + kc)*128 + n)*8 + widx;
        g_wpack[base*2 + half] = l;
    }
}

__global__ void zero_kernel(float* __restrict__ upd) {
    int i = blockIdx.x * blockDim.x + threadIdx.x;
    if (i < UPDSZ) upd[i] = 0.f;
    if (i < K_) g_kcnt[i] = 0;
    if (i == 0) g_ambcnt = 0;
}

// ---------------------------------------------------------------------------
// conv_mma: HMMA GEMM. CTA = (b, 2 output rows) -> 128 pos x 128 k.
// ---------------------------------------------------------------------------
#define SOFF_BIAS 0
#define SOFF_TH   1024
#define SOFF_TL   33792
#define SOFF_W    66560
#define SOFF_D    1024
#define SMEM_BYTES 99328

__global__ void __launch_bounds__(256) conv_mma_kernel(
    const float* __restrict__ bias, float* __restrict__ y)
{
    extern __shared__ unsigned char smem[];
    const uint32_t sb = smem_to_u32(smem);
    const int tid = threadIdx.x;
    const int l   = tid & 31;
    const int wid = tid >> 5;
    const int wm  = wid >> 2;
    const int wn  = wid & 3;
    const int b   = blockIdx.y;
    const int oh0 = blockIdx.x * 2;

    if (tid < 128) ((float*)(smem + SOFF_BIAS))[tid] = bias[tid];

    for (int idx = tid; idx < C_*4*16; idx += 256) {
        int c    = idx >> 6;
        int row  = (idx >> 4) & 3;
        int col4 = (idx & 15) * 4;
        size_t gi = (((size_t)b*C_ + c)*H_ + (oh0 + row))*W_ + col4;
        const __nv_bfloat16* ph = g_xh + gi;
        const __nv_bfloat16* pl = g_xl + gi;
        #pragma unroll
        for (int q = 0; q < 4; q++) {
            int col = col4 + q;
            int rowIdx = row*64 + col;
            uint32_t off = (uint32_t)(rowIdx*128 + c*2) ^ (uint32_t)((rowIdx & 7) << 4);
            *(__nv_bfloat16*)(smem + SOFF_TH + off) = ph[q];
            *(__nv_bfloat16*)(smem + SOFF_TL + off) = pl[q];
        }
    }

    float acc[4][4][4] = {};
    const int lrow_lo = (l & 7) + ((l >> 3) & 1) * 8;
    const uint32_t khalf = (uint32_t)((l >> 4) * 16);

    #pragma unroll 1
    for (int s = 0; s < 9; s++) {
        const int i = s / 3, j = s - 3*(s/3);
        __syncthreads();
        {
            const uint4* src = (const uint4*)((const __nv_bfloat16*)g_wpack + (size_t)s*16384);
            uint4* dst = (uint4*)(smem + SOFF_W);
            #pragma unroll
            for (int t = 0; t < 8; t++) dst[tid + t*256] = src[tid + t*256];
        }
        __syncthreads();

        uint32_t abase[4], asw[4];
        #pragma unroll
        for (int mt = 0; mt < 4; mt++) {
            int m  = wm*64 + mt*16 + lrow_lo;
            int nr = m >> 6, nc = m & 63;
            int pc = nc + j; if (pc > 63) pc = 63;
            int rowIdx = (nr + i)*64 + pc;
            abase[mt] = sb + SOFF_TH + (uint32_t)(rowIdx*128);
            asw[mt]   = (uint32_t)((rowIdx & 7) << 4);
        }

        const uint32_t swb = sb + SOFF_W;
        #pragma unroll 1
        for (int kc = 0; kc < 4; kc++) {
            const uint32_t koff = (uint32_t)kc * 32;
            uint32_t ah[4][4], bh[4][2];
            #pragma unroll
            for (int mt = 0; mt < 4; mt++)
                ldmx4(ah[mt], abase[mt] + ((khalf + koff) ^ asw[mt]));
            #pragma unroll
            for (int nt = 0; nt < 4; nt++) {
                int n = wn*32 + nt*8 + (l >> 2);
                lds64(bh[nt], swb + (uint32_t)((((0*4 + kc)*128 + n)*8 + (l & 3)*2) * 4));
            }
            #pragma unroll
            for (int mt = 0; mt < 4; mt++)
                #pragma unroll
                for (int nt = 0; nt < 4; nt++)
                    mma16816(acc[mt][nt], ah[mt], bh[nt]);
            {
                uint32_t al[4][4];
                #pragma unroll
                for (int mt = 0; mt < 4; mt++)
                    ldmx4(al[mt], abase[mt] + 32768 + ((khalf + koff) ^ asw[mt]));
                #pragma unroll
                for (int mt = 0; mt < 4; mt++)
                    #pragma unroll
                    for (int nt = 0; nt < 4; nt++)
                        mma16816(acc[mt][nt], al[mt], bh[nt]);
            }
            {
                uint32_t bl[4][2];
                #pragma unroll
                for (int nt = 0; nt < 4; nt++) {
                    int n = wn*32 + nt*8 + (l >> 2);
                    lds64(bl[nt], swb + (uint32_t)((((1*4 + kc)*128 + n)*8 + (l & 3)*2) * 4));
                }
                #pragma unroll
                for (int mt = 0; mt < 4; mt++)
                    #pragma unroll
                    for (int nt = 0; nt < 4; nt++)
                        mma16816(acc[mt][nt], ah[mt], bl[nt]);
            }
        }
    }

    // ---- epilogue: frags -> smem D[128][130] ----
    __syncthreads();
    float* D = (float*)(smem + SOFF_D);
    {
        const int r  = l >> 2;
        const int cq = (l & 3) * 2;
        #pragma unroll
        for (int mt = 0; mt < 4; mt++)
            #pragma unroll
            for (int nt = 0; nt < 4; nt++) {
                int pos = wm*64 + mt*16 + r;
                int k   = wn*32 + nt*8 + cq;
                *(float2*)&D[pos*130 + k]       = make_float2(acc[mt][nt][0], acc[mt][nt][1]);
                *(float2*)&D[(pos + 8)*130 + k] = make_float2(acc[mt][nt][2], acc[mt][nt][3]);
            }
    }
    __syncthreads();

    // ---- per-thread: bias + top-2 argmax + y store; flag near-ties ----
    {
        const int p2   = tid >> 1;
        const int kh2  = (tid & 1) * 64;
        const int nrow = p2 >> 6, ncol = p2 & 63;
        const int oh = oh0 + nrow, ow = ncol;
        const bool valid = (ncol < OW);
        const float* bs = (const float*)(smem + SOFF_BIAS);
        float v1 = -INFINITY, v2 = -INFINITY;
        int   k1 = 0, k2 = 0;
        float* yb = y + ((size_t)b*K_)*OH*OW + (size_t)oh*OW + ow;
        #pragma unroll 4
        for (int k = kh2; k < kh2 + 64; k += 2) {
            float2 d = *(float2*)&D[p2*130 + k];
            float a0 = d.x + bs[k];
            float a1 = d.y + bs[k+1];
            if (a0 > v1) { v2 = v1; k2 = k1; v1 = a0; k1 = k; }
            else if (a0 > v2) { v2 = a0; k2 = k; }
            if (a1 > v1) { v2 = v1; k2 = k1; v1 = a1; k1 = k + 1; }
            else if (a1 > v2) { v2 = a1; k2 = k + 1; }
            if (valid) {
                yb[(size_t)k*OH*OW]     = a0;
                yb[(size_t)(k+1)*OH*OW] = a1;
            }
        }
        __syncthreads();
        float* rv = (float*)(smem + SOFF_D);
        int*   rk = (int*)(smem + SOFF_D + 4096);
        rv[tid*2] = v1; rv[tid*2+1] = v2;
        rk[tid*2] = k1; rk[tid*2+1] = k2;
        __syncthreads();
        if ((tid & 1) == 0 && valid) {
            float w1 = rv[(tid+1)*2], w2 = rv[(tid+1)*2+1];
            int   j1 = rk[(tid+1)*2], j2 = rk[(tid+1)*2+1];
            float t1, t2; int m1, m2;
            if (w1 > v1) { t1 = w1; m1 = j1; t2 = (v1 > w2) ? v1 : w2; m2 = (v1 > w2) ? k1 : j2; }
            else         { t1 = v1; m1 = k1; t2 = (w1 > v2) ? w1 : v2; m2 = (w1 > v2) ? j1 : k2; }
            int pos = (b*OH + oh)*OW + ow;
            g_winners[pos] = m1;
            if (t1 - t2 < 4e-3f) {
                unsigned int slot = atomicAdd(&g_ambcnt, 1u);
                if (slot < AMB_CAP)
                    g_amb[slot] = (unsigned int)pos | ((unsigned int)m1 << 17)
                                                   | ((unsigned int)m2 << 24);
            }
        }
    }
}

// ---------------------------------------------------------------------------
// refine: R2 replay (sequential fp32 fmaf, (c,kh,kw) order, first-max ties).
// Reproduces the winner field that passed at 5.7e-7.
// ---------------------------------------------------------------------------
__global__ void __launch_bounds__(128) refine_kernel(const float* __restrict__ x) {
    unsigned int total = g_ambcnt;
    if (total > AMB_CAP) total = AMB_CAP;
    unsigned int stride = gridDim.x * blockDim.x;
    for (unsigned int e = blockIdx.x * blockDim.x + threadIdx.x; e < total; e += stride) {
        unsigned int ent = g_amb[e];
        int pos = (int)(ent & 0x1FFFF);
        int ka  = (int)((ent >> 17) & 0x7F);
        int kb  = (int)((ent >> 24) & 0x7F);
        int bb = pos / (OH*OW);
        int r  = pos - bb*(OH*OW);
        int oh = r / OW;
        int ow = r - oh*OW;
        const float* xb = x + (size_t)bb*C_*H_*W_ + (size_t)oh*W_ + ow;
        const float* wa = g_wnf + ka*576;
        const float* wb = g_wnf + kb*576;
        float sa = 0.f, sb2 = 0.f;
        #pragma unroll 1
        for (int c = 0; c < C_; c++) {
            const float* xc = xb + (size_t)c*H_*W_;
            const float* wac = wa + c*9;
            const float* wbc = wb + c*9;
            #pragma unroll
            for (int ii = 0; ii < 3; ii++)
                #pragma unroll
                for (int jj = 0; jj < 3; jj++) {
                    float xv = xc[ii*W_ + jj];
                    sa  = fmaf(xv, wac[ii*3 + jj], sa);
                    sb2 = fmaf(xv, wbc[ii*3 + jj], sb2);
                }
        }
        int klo, khi; float dlo, dhi;
        if (ka < kb) { klo = ka; khi = kb; dlo = sa; dhi = sb2; }
        else         { klo = kb; khi = ka; dlo = sb2; dhi = sa; }
        g_winners[pos] = (dhi > dlo) ? khi : klo;
    }
}

// ---------------------------------------------------------------------------
__global__ void __launch_bounds__(256) bucket_kernel() {
    int pos = blockIdx.x * blockDim.x + threadIdx.x;
    if (pos >= NPOS) return;
    int k = g_winners[pos];
    int slot = atomicAdd(&g_kcnt[k], 1);
    g_klist[(size_t)k*NPOS + slot] = pos;
}

// ---------------------------------------------------------------------------
// hebb: bucketed, NHWC-coalesced. Thread element f = ij*64 + c so each
// warp reads 32 consecutive channels of one patch cell (128B lines).
// ---------------------------------------------------------------------------
__global__ void __launch_bounds__(256) hebb_kernel(float* __restrict__ upd) {
    const int k   = blockIdx.x;
    const int ch  = blockIdx.y;
    const int tid = threadIdx.x;
    const int n   = g_kcnt[k];
    const int lo  = (int)((long long)n * ch / 16);
    const int hi  = (int)((long long)n * (ch + 1) / 16);

    // f -> (ij, c): f = ij*64 + c. NHWC offset = (ii*W + jj)*64 + c.
    const int f0 = tid,       ij0 = f0 >> 6, c0 = f0 & 63;
    const int f1 = tid + 256, ij1 = f1 >> 6, c1 = f1 & 63;
    const int f2 = tid + 512, ij2 = f2 >> 6, c2 = f2 & 63;   // valid iff tid < 64
    const int off0 = ((ij0/3)*W_ + (ij0%3))*64 + c0;
    const int off1 = ((ij1/3)*W_ + (ij1%3))*64 + c1;
    const int off2 = (f2 < 576) ? ((ij2/3)*W_ + (ij2%3))*64 + c2 : 0;
    float a0 = 0.f, a1 = 0.f, a2 = 0.f;

    const int* list = g_klist + (size_t)k*NPOS;
    #pragma unroll 1
    for (int t = lo; t < hi; t++) {
        int pos = list[t];
        int bb = pos / (OH*OW);
        int r  = pos - bb*(OH*OW);
        int oh = r / OW;
        int ow = r - oh*OW;
        const float* xb = g_xt + ((((size_t)bb*H_ + oh)*W_ + ow) << 6);
        a0 += xb[off0];
        a1 += xb[off1];
        if (f2 < 576) a2 += xb[off2];
    }
    const float s = 1.0f / (123008.0f + 1e-8f);
    if (lo < hi) {
        atomicAdd(&upd[k*576 + c0*9 + ij0], a0 * s);
        atomicAdd(&upd[k*576 + c1*9 + ij1], a1 * s);
        if (f2 < 576) atomicAdd(&upd[k*576 + c2*9 + ij2], a2 * s);
    }
}

// ---------------------------------------------------------------------------
extern "C" void kernel_launch(void* const* d_in, const int* in_sizes, int n_in,
                              void* d_out, int out_size) {
    const float* x    = (const float*)d_in[0];
    const float* w    = (const float*)d_in[1];
    const float* bias = (const float*)d_in[2];
    float* y   = (float*)d_out;
    float* upd = y + YSZ;

    cudaFuncSetAttribute(conv_mma_kernel,
                         cudaFuncAttributeMaxDynamicSharedMemorySize, SMEM_BYTES);

    prep_x_kernel<<<(int)(((size_t)B_*C_*H_*W_ + 255)/256), 256>>>(x);
    transpose_kernel<<<B_*H_, 256>>>(x);
    prep_w_kernel<<<9, 128>>>(w);
    zero_kernel<<<(UPDSZ + 255)/256, 256>>>(upd);
    conv_mma_kernel<<<dim3(OH/2, B_), 256, SMEM_BYTES>>>(bias, y);
    refine_kernel<<<128, 128>>>(x);
    bucket_kernel<<<(NPOS + 255)/256, 256>>>();
    hebb_kernel<<<dim3(K_, 16), 256>>>(upd);
}